// round 16
// baseline (speedup 1.0000x reference)
#include <cuda_runtime.h>

#define NB 8
#define NS 1024
#define ND 128
#define NBS (NB*NS)   // 8192
#define NCH 256       // time chunks
#define CLEN 4        // steps per chunk

// scratch (static __device__ allocations only, per harness rules)
__device__ float g_K[NBS*ND];
__device__ float g_V[NBS*ND];
__device__ float g_Q[NBS*ND];
__device__ float g_G[NBS*3];
__device__ float g_Err[NBS*ND];
__device__ float g_cM[NBS];
__device__ float g_cS[NBS];
__device__ float g_comp[NB*NCH*6*ND];   // per-chunk 2x2 affine maps
__device__ float g_start[NB*NCH*2*ND];  // per-chunk start states
__device__ int   g_tstart[NB];

// ---------------------------------------------------------------------------
// packed fp32x2 helpers (Blackwell FFMA2 path, PTX-only)
// ---------------------------------------------------------------------------
__device__ __forceinline__ unsigned long long fma2(unsigned long long a,
                                                   unsigned long long b,
                                                   unsigned long long c) {
    unsigned long long d;
    asm("fma.rn.f32x2 %0, %1, %2, %3;" : "=l"(d) : "l"(a), "l"(b), "l"(c));
    return d;
}
__device__ __forceinline__ float pairsum(unsigned long long v) {
    float lo, hi;
    asm("mov.b64 {%0, %1}, %2;" : "=f"(lo), "=f"(hi) : "l"(v));
    return lo + hi;
}

// ---------------------------------------------------------------------------
// Launch 1: projections K/V/Q (f32x2 packed FMA) + gates, one grid.
// grid (128, 4): y<3 -> proj row-tile for matrix y; y==3 -> gates for 64 rows.
// ---------------------------------------------------------------------------
__global__ void __launch_bounds__(256, 2)
proj_gates_kernel(const float* __restrict__ x,
                  const float* __restrict__ Wk,
                  const float* __restrict__ Wv,
                  const float* __restrict__ Wq,
                  const float* __restrict__ Wg,
                  const float* __restrict__ bg) {
    const int tid = threadIdx.x;
    const int mat = blockIdx.y;

    if (mat == 3) {
        // ---- gates: sigmoid(x @ Wg + bg); 8 warps x 8 rows = 64 rows/block
        const int warp = tid >> 5, lane = tid & 31;
        const float b0 = bg[0], b1 = bg[1], b2 = bg[2];
        const int kb = lane * 4;
        float wr0[4], wr1[4], wr2[4];
#pragma unroll
        for (int j = 0; j < 4; j++) {
            const float* wr = Wg + (kb + j) * 3;
            wr0[j] = wr[0]; wr1[j] = wr[1]; wr2[j] = wr[2];
        }
#pragma unroll
        for (int r = 0; r < 8; r++) {
            int row = blockIdx.x * 64 + warp * 8 + r;
            float4 xv = ((const float4*)x)[row * 32 + lane];
            float xr[4] = {xv.x, xv.y, xv.z, xv.w};
            float d0 = 0.f, d1 = 0.f, d2 = 0.f;
#pragma unroll
            for (int j = 0; j < 4; j++) {
                d0 = fmaf(xr[j], wr0[j], d0);
                d1 = fmaf(xr[j], wr1[j], d1);
                d2 = fmaf(xr[j], wr2[j], d2);
            }
#pragma unroll
            for (int off = 16; off; off >>= 1) {
                d0 += __shfl_xor_sync(0xffffffffu, d0, off);
                d1 += __shfl_xor_sync(0xffffffffu, d1, off);
                d2 += __shfl_xor_sync(0xffffffffu, d2, off);
            }
            if (lane == 0) {
                g_G[row * 3 + 0] = 1.f / (1.f + expf(-(d0 + b0)));
                g_G[row * 3 + 1] = 1.f / (1.f + expf(-(d1 + b1)));
                g_G[row * 3 + 2] = 1.f / (1.f + expf(-(d2 + b2)));
            }
        }
        return;
    }

    // ---- projection path: 64 rows x 128 cols per block
    extern __shared__ float smem[];
    float*  xs = smem;                       // 64 x 128 floats (32KB)
    float4* wt = (float4*)(smem + 64 * ND);  // 32 x 128 units of 16B (64KB)

    const int tile = blockIdx.x;
    const float* __restrict__ W = (mat == 0) ? Wk : (mat == 1) ? Wv : Wq;
    float* out = (mat == 0) ? g_K : (mat == 1) ? g_V : g_Q;

    const float4* x4 = (const float4*)(x + (size_t)tile * 64 * ND);
#pragma unroll
    for (int j = 0; j < 8; j++) {
        int idx = tid + j * 256;            // 2048 float4s
        ((float4*)xs)[idx] = x4[idx];
    }
#pragma unroll
    for (int j = 0; j < 16; j++) {
        int u = tid + j * 256;              // 4096 units
        int kq = u >> 7, c = u & 127;
        float4 wv;
        wv.x = W[(4 * kq + 0) * ND + c];
        wv.y = W[(4 * kq + 1) * ND + c];
        wv.z = W[(4 * kq + 2) * ND + c];
        wv.w = W[(4 * kq + 3) * ND + c];
        wt[u] = wv;
    }
    __syncthreads();

    const int lane = tid & 31;
    const int rb   = (tid >> 5) * 8;        // 8 rows per thread
    unsigned long long acc[8][4];
#pragma unroll
    for (int r = 0; r < 8; r++)
#pragma unroll
        for (int c = 0; c < 4; c++) acc[r][c] = 0ull;

#pragma unroll 4
    for (int kq = 0; kq < 32; kq++) {
        ulonglong2 xp[8];
#pragma unroll
        for (int r = 0; r < 8; r++)
            xp[r] = *(const ulonglong2*)&xs[(rb + r) * ND + 4 * kq];
#pragma unroll
        for (int cc = 0; cc < 4; cc++) {
            ulonglong2 wp = ((const ulonglong2*)wt)[kq * ND + lane + 32 * cc];
#pragma unroll
            for (int r = 0; r < 8; r++) {
                acc[r][cc] = fma2(xp[r].x, wp.x, acc[r][cc]);
                acc[r][cc] = fma2(xp[r].y, wp.y, acc[r][cc]);
            }
        }
    }
#pragma unroll
    for (int r = 0; r < 8; r++)
#pragma unroll
        for (int cc = 0; cc < 4; cc++)
            out[(size_t)(tile * 64 + rb + r) * ND + lane + 32 * cc] =
                pairsum(acc[r][cc]);
}

// ---------------------------------------------------------------------------
// Launch 2: grid (NCH+1, 8), 128 threads.
//   bx < NCH  -> forward-scan phase 1 (per-chunk 2x2 affine map, CLEN=4)
//   bx == NCH -> backward suffix scans -> cM, cS, tstart (per batch)
// ---------------------------------------------------------------------------
__global__ void bwd_p1_kernel() {
    const int bx = blockIdx.x, b = blockIdx.y;

    if (bx < NCH) {
        // ---------------- phase 1: chunk affine maps ----------------
        const int ch = bx, d = threadIdx.x;
        const int t0 = ch * CLEN;
        __shared__ float sg[CLEN * 3];
        if (d < CLEN * 3) sg[d] = g_G[(size_t)b * NS * 3 + t0 * 3 + d];
        __syncthreads();

        const size_t base = (size_t)b * NS * ND + d;
        float kv[CLEN], vv[CLEN];
#pragma unroll
        for (int j = 0; j < CLEN; j++) kv[j] = g_K[base + (size_t)(t0 + j) * ND];
#pragma unroll
        for (int j = 0; j < CLEN; j++) vv[j] = g_V[base + (size_t)(t0 + j) * ND];

        float m00 = 1.f, m01 = 0.f, m10 = 0.f, m11 = 1.f, w0 = 0.f, w1 = 0.f;
#pragma unroll
        for (int j = 0; j < CLEN; j++) {
            float k = kv[j], v = vv[j];
            float a = sg[j * 3 + 0], e = sg[j * 3 + 1], th = sg[j * 3 + 2];
            float thk2 = th * (k * k);
            float p = (1.f - a) - thk2;
            float q = -thk2;
            float c = th * k * v;
            float e10 = e * m10, e11 = e * m11, ev = fmaf(e, w1, c);
            float n00 = fmaf(p, m00, e10), n01 = fmaf(p, m01, e11);
            float n10 = fmaf(q, m00, e10), n11 = fmaf(q, m01, e11);
            float nv0 = fmaf(p, w0, ev),   nv1 = fmaf(q, w0, ev);
            m00 = n00; m01 = n01; m10 = n10; m11 = n11; w0 = nv0; w1 = nv1;
        }
        const size_t cb = ((size_t)(b * NCH + ch) * 6) * ND + d;
        g_comp[cb + 0 * ND] = m00; g_comp[cb + 1 * ND] = m01;
        g_comp[cb + 2 * ND] = m10; g_comp[cb + 3 * ND] = m11;
        g_comp[cb + 4 * ND] = w0;  g_comp[cb + 5 * ND] = w1;
        return;
    }

    // ---------------- backward suffix scans (per batch) ----------------
    const int i = threadIdx.x;          // 0..127, chunk of 8 timesteps
    const int lo = i * 8;
    const float* __restrict__ gb = g_G + (size_t)b * NS * 3;

    float ev[8], av[8], thv[8];
#pragma unroll
    for (int j = 0; j < 8; j++) {
        av[j]  = 1.f - gb[(lo + j) * 3 + 0];
        ev[j]  = gb[(lo + j) * 3 + 1];
        thv[j] = gb[(lo + j) * 3 + 2];
    }
    float e_next = (lo + 8 < NS) ? gb[(lo + 8) * 3 + 1] : 0.f;

    __shared__ float sLe[128], sLa[128], sAa[128], sBa[128];
    __shared__ float sTe[128], sTa[128], sTw[128];
    __shared__ int   smin[4];

    float Le = 1.f, La = 1.f;
#pragma unroll
    for (int j = 0; j < 8; j++) { Le *= ev[j]; La *= av[j]; }
    sLe[i] = Le; sLa[i] = La;
    __syncthreads();
    if (i == 0) {       // exclusive suffix products across chunks
        float te = 1.f, ta = 1.f;
        for (int c = 127; c >= 0; c--) {
            sTe[c] = te; sTa[c] = ta;
            te *= sLe[c]; ta *= sLa[c];
        }
    }
    __syncthreads();

    float E[8], A[8];
    {
        float re = sTe[i], ra = sTa[i];
#pragma unroll
        for (int j = 7; j >= 0; j--) {
            E[j] = re; A[j] = ra;
            re *= ev[j]; ra *= av[j];
        }
    }
    float Aa = 1.f, Ba = 0.f;
#pragma unroll
    for (int j = 7; j >= 0; j--) {
        float al = (j == 7) ? e_next : ev[j + 1];
        Aa = al * Aa;
        Ba = fmaf(al, Ba, A[j]);
    }
    sAa[i] = Aa; sBa[i] = Ba;
    __syncthreads();
    if (i == 0) {       // tail W per chunk
        float w = 0.f;
        for (int c = 127; c >= 0; c--) {
            sTw[c] = w;
            w = fmaf(sAa[c], w, sBa[c]);
        }
    }
    __syncthreads();

    float w = sTw[i];
    int flag = 0;
#pragma unroll
    for (int j = 7; j >= 0; j--) {
        float al = (j == 7) ? e_next : ev[j + 1];
        w = fmaf(al, w, A[j]);                  // = W_{lo+j}
        float cm = -thv[j] * w;
        float cs = -thv[j] * E[j];
        g_cM[b * NS + lo + j] = cm;
        g_cS[b * NS + lo + j] = cs;
        if (fabsf(cm) > 1e-18f || fabsf(cs) > 1e-18f) flag = 1;
    }
    int myv = flag ? lo : 0x7FFFFFFF;
    myv = __reduce_min_sync(0xffffffffu, myv);
    if ((i & 31) == 0) smin[i >> 5] = myv;
    __syncthreads();
    if (i == 0) {
        int r = smin[0];
        r = min(r, smin[1]); r = min(r, smin[2]); r = min(r, smin[3]);
        g_tstart[b] = r;
    }
}

// ---------------------------------------------------------------------------
// Launch 3: chunk-boundary start states, hierarchical.
// grid 8 (b), 1024 threads = 8 subs x 128 d. Each sub covers 32 chunks.
// ---------------------------------------------------------------------------
__global__ void scan_p2() {
    const int b   = blockIdx.x;
    const int d   = threadIdx.x & 127;
    const int sub = threadIdx.x >> 7;     // 0..7

    __shared__ float scomp[8][128][6];
    __shared__ float sx[8][128][2];

    // pass A: compose this sub-block's 32 chunk maps
    {
        float r00 = 1.f, r01 = 0.f, r10 = 0.f, r11 = 1.f, rv0 = 0.f, rv1 = 0.f;
#pragma unroll 8
        for (int i = 0; i < 32; i++) {
            const int c = sub * 32 + i;
            const size_t cb = ((size_t)(b * NCH + c) * 6) * ND + d;
            float t00 = g_comp[cb + 0 * ND], t01 = g_comp[cb + 1 * ND];
            float t10 = g_comp[cb + 2 * ND], t11 = g_comp[cb + 3 * ND];
            float tv0 = g_comp[cb + 4 * ND], tv1 = g_comp[cb + 5 * ND];
            float n00 = fmaf(t00, r00, t01 * r10);
            float n01 = fmaf(t00, r01, t01 * r11);
            float n10 = fmaf(t10, r00, t11 * r10);
            float n11 = fmaf(t10, r01, t11 * r11);
            float nv0 = fmaf(t00, rv0, fmaf(t01, rv1, tv0));
            float nv1 = fmaf(t10, rv0, fmaf(t11, rv1, tv1));
            r00 = n00; r01 = n01; r10 = n10; r11 = n11; rv0 = nv0; rv1 = nv1;
        }
        scomp[sub][d][0] = r00; scomp[sub][d][1] = r01;
        scomp[sub][d][2] = r10; scomp[sub][d][3] = r11;
        scomp[sub][d][4] = rv0; scomp[sub][d][5] = rv1;
    }
    __syncthreads();

    // serial across 8 subs (128 threads, one per d)
    if (threadIdx.x < 128) {
        float x0 = 0.f, x1 = 0.f;
#pragma unroll
        for (int s = 0; s < 8; s++) {
            sx[s][d][0] = x0; sx[s][d][1] = x1;
            float t00 = scomp[s][d][0], t01 = scomp[s][d][1];
            float t10 = scomp[s][d][2], t11 = scomp[s][d][3];
            float nx0 = fmaf(t00, x0, fmaf(t01, x1, scomp[s][d][4]));
            float nx1 = fmaf(t10, x0, fmaf(t11, x1, scomp[s][d][5]));
            x0 = nx0; x1 = nx1;
        }
    }
    __syncthreads();

    // pass B: walk 32 chunks, emit per-chunk start state
    {
        float x0 = sx[sub][d][0], x1 = sx[sub][d][1];
#pragma unroll 8
        for (int i = 0; i < 32; i++) {
            const int c = sub * 32 + i;
            const size_t sb = ((size_t)(b * NCH + c) * 2) * ND + d;
            g_start[sb] = x0; g_start[sb + ND] = x1;
            const size_t cb = ((size_t)(b * NCH + c) * 6) * ND + d;
            float t00 = g_comp[cb + 0 * ND], t01 = g_comp[cb + 1 * ND];
            float t10 = g_comp[cb + 2 * ND], t11 = g_comp[cb + 3 * ND];
            float nx0 = fmaf(t00, x0, fmaf(t01, x1, g_comp[cb + 4 * ND]));
            float nx1 = fmaf(t10, x0, fmaf(t11, x1, g_comp[cb + 5 * ND]));
            x0 = nx0; x1 = nx1;
        }
    }
}

// ---------------------------------------------------------------------------
// Launch 4: replay each chunk from its start state, emit y / err.
// grid (256, 8), 128 threads. Err stores gated by per-batch active range.
// ---------------------------------------------------------------------------
__global__ void scan_p3(float* __restrict__ y_out) {
    const int ch = blockIdx.x, b = blockIdx.y;
    const int d  = threadIdx.x;
    const int t0 = ch * CLEN;
    __shared__ float sg[CLEN * 3];
    __shared__ int sts;
    if (d < CLEN * 3) sg[d] = g_G[(size_t)b * NS * 3 + t0 * 3 + d];
    if (d == 127) sts = g_tstart[b];
    __syncthreads();

    int ts = sts;
    if (ts > NS) ts = NS;
    const bool storeErr = (t0 + CLEN) > (ts & ~31);

    const size_t base = (size_t)b * NS * ND + d;
    const size_t sb = ((size_t)(b * NCH + ch) * 2) * ND + d;
    float m = g_start[sb], s = g_start[sb + ND];

    float kv[CLEN], vv[CLEN], qv[CLEN];
#pragma unroll
    for (int j = 0; j < CLEN; j++) kv[j] = g_K[base + (size_t)(t0 + j) * ND];
#pragma unroll
    for (int j = 0; j < CLEN; j++) vv[j] = g_V[base + (size_t)(t0 + j) * ND];
#pragma unroll
    for (int j = 0; j < CLEN; j++) qv[j] = g_Q[base + (size_t)(t0 + j) * ND];

#pragma unroll
    for (int j = 0; j < CLEN; j++) {
        const size_t off = base + (size_t)(t0 + j) * ND;
        float a = sg[j * 3 + 0], e = sg[j * 3 + 1], th = sg[j * 3 + 2];
        y_out[off] = qv[j] * m;
        float err = fmaf(kv[j], m, -vv[j]);
        if (storeErr) g_Err[off] = err;
        s = fmaf(e, s, -th * (kv[j] * err));
        m = fmaf(1.f - a, m, s);
    }
}

// ---------------------------------------------------------------------------
// Launch 5: M_final/S_final = (c o K)^T @ Err over active range [t_start, NS).
// grid (2 col-halves, 2 which, 8 b), 256 threads, no atomics.
// ---------------------------------------------------------------------------
__global__ void final_kernel(float* __restrict__ out) {
    const int colh  = blockIdx.x;
    const int which = blockIdx.y;     // 0 -> M (cM), 1 -> S (cS)
    const int b     = blockIdx.z;
    const float* __restrict__ cw = which ? g_cS : g_cM;
    const int tid = threadIdx.x;

    int ts = g_tstart[b];
    if (ts > NS) ts = NS;
    int t0 = ts & ~31;

    __shared__ float As[32][128];
    __shared__ float Bs[32][64];

    const int tx = tid & 15, ty = tid >> 4;
    const int i0 = ty * 8, j0 = tx * 4;
    float acc[8][4];
#pragma unroll
    for (int r = 0; r < 8; r++)
#pragma unroll
        for (int c = 0; c < 4; c++) acc[r][c] = 0.f;

    for (int tc = t0; tc < NS; tc += 32) {
        __syncthreads();
        for (int idx = tid; idx < 32 * 128; idx += 256) {
            int kk = idx >> 7, col = idx & 127;
            size_t t = (size_t)b * NS + tc + kk;
            As[kk][col] = cw[t] * g_K[t * ND + col];
        }
        for (int idx = tid; idx < 32 * 64; idx += 256) {
            int kk = idx >> 6, col = idx & 63;
            size_t t = (size_t)b * NS + tc + kk;
            Bs[kk][col] = g_Err[t * ND + colh * 64 + col];
        }
        __syncthreads();

#pragma unroll 8
        for (int kk = 0; kk < 32; kk++) {
            float avv[8], bvv[4];
            float4 a0 = *(const float4*)&As[kk][i0];
            float4 a1 = *(const float4*)&As[kk][i0 + 4];
            float4 b0 = *(const float4*)&Bs[kk][j0];
            avv[0]=a0.x; avv[1]=a0.y; avv[2]=a0.z; avv[3]=a0.w;
            avv[4]=a1.x; avv[5]=a1.y; avv[6]=a1.z; avv[7]=a1.w;
            bvv[0]=b0.x; bvv[1]=b0.y; bvv[2]=b0.z; bvv[3]=b0.w;
#pragma unroll
            for (int r = 0; r < 8; r++)
#pragma unroll
                for (int c = 0; c < 4; c++)
                    acc[r][c] = fmaf(avv[r], bvv[c], acc[r][c]);
        }
    }

    float* o = out + (size_t)NBS * ND + (size_t)which * NB * ND * ND
                 + (size_t)b * ND * ND + colh * 64;
#pragma unroll
    for (int r = 0; r < 8; r++) {
        float4 res = make_float4(acc[r][0], acc[r][1], acc[r][2], acc[r][3]);
        *(float4*)&o[(i0 + r) * ND + j0] = res;
    }
}

// ---------------------------------------------------------------------------
extern "C" void kernel_launch(void* const* d_in, const int* in_sizes, int n_in,
                              void* d_out, int out_size) {
    const float* x  = (const float*)d_in[0];
    const float* Wk = (const float*)d_in[1];
    const float* Wv = (const float*)d_in[2];
    const float* Wq = (const float*)d_in[3];
    const float* Wg = (const float*)d_in[4];
    const float* bg = (const float*)d_in[5];
    float* out = (float*)d_out;

    const int proj_smem = (64 * ND + 32 * ND * 4) * (int)sizeof(float); // 96KB
    cudaFuncSetAttribute(proj_gates_kernel,
                         cudaFuncAttributeMaxDynamicSharedMemorySize, proj_smem);

    proj_gates_kernel<<<dim3(128, 4), 256, proj_smem>>>(x, Wk, Wv, Wq, Wg, bg);
    bwd_p1_kernel<<<dim3(NCH + 1, NB), 128>>>();
    scan_p2<<<NB, 1024>>>();
    scan_p3<<<dim3(NCH, NB), 128>>>(out);
    final_kernel<<<dim3(2, 2, 8), 256>>>(out);
}

// round 17
// speedup vs baseline: 1.1809x; 1.1809x over previous
#include <cuda_runtime.h>

#define NB 8
#define NS 1024
#define ND 128
#define NBS (NB*NS)   // 8192
#define NCH 128       // time chunks
#define CLEN 8        // steps per chunk

// scratch (static __device__ allocations only, per harness rules)
__device__ float g_K[NBS*ND];
__device__ float g_V[NBS*ND];
__device__ float g_Q[NBS*ND];
__device__ float g_G[NBS*3];
__device__ float g_Err[NBS*ND];
__device__ float g_cM[NBS];
__device__ float g_cS[NBS];
__device__ float g_comp[NB*NCH*6*ND];   // per-chunk 2x2 affine maps
__device__ float g_start[NB*NCH*2*ND];  // per-chunk start states
__device__ int   g_tstart[NB];

// ---------------------------------------------------------------------------
// packed fp32x2 helpers (Blackwell FFMA2 path, PTX-only)
// ---------------------------------------------------------------------------
__device__ __forceinline__ unsigned long long fma2(unsigned long long a,
                                                   unsigned long long b,
                                                   unsigned long long c) {
    unsigned long long d;
    asm("fma.rn.f32x2 %0, %1, %2, %3;" : "=l"(d) : "l"(a), "l"(b), "l"(c));
    return d;
}
__device__ __forceinline__ float pairsum(unsigned long long v) {
    float lo, hi;
    asm("mov.b64 {%0, %1}, %2;" : "=f"(lo), "=f"(hi) : "l"(v));
    return lo + hi;
}

// ---------------------------------------------------------------------------
// Launch 1: projections K/V/Q (f32x2 packed FMA) + gates, one grid.
// grid (128, 4): y<3 -> proj row-tile for matrix y; y==3 -> gates for 64 rows.
// ---------------------------------------------------------------------------
__global__ void __launch_bounds__(256, 2)
proj_gates_kernel(const float* __restrict__ x,
                  const float* __restrict__ Wk,
                  const float* __restrict__ Wv,
                  const float* __restrict__ Wq,
                  const float* __restrict__ Wg,
                  const float* __restrict__ bg) {
    const int tid = threadIdx.x;
    const int mat = blockIdx.y;

    if (mat == 3) {
        // ---- gates: sigmoid(x @ Wg + bg); 8 warps x 8 rows = 64 rows/block
        const int warp = tid >> 5, lane = tid & 31;
        const float b0 = bg[0], b1 = bg[1], b2 = bg[2];
        const int kb = lane * 4;
        float wr0[4], wr1[4], wr2[4];
#pragma unroll
        for (int j = 0; j < 4; j++) {
            const float* wr = Wg + (kb + j) * 3;
            wr0[j] = wr[0]; wr1[j] = wr[1]; wr2[j] = wr[2];
        }
#pragma unroll
        for (int r = 0; r < 8; r++) {
            int row = blockIdx.x * 64 + warp * 8 + r;
            float4 xv = ((const float4*)x)[row * 32 + lane];
            float xr[4] = {xv.x, xv.y, xv.z, xv.w};
            float d0 = 0.f, d1 = 0.f, d2 = 0.f;
#pragma unroll
            for (int j = 0; j < 4; j++) {
                d0 = fmaf(xr[j], wr0[j], d0);
                d1 = fmaf(xr[j], wr1[j], d1);
                d2 = fmaf(xr[j], wr2[j], d2);
            }
#pragma unroll
            for (int off = 16; off; off >>= 1) {
                d0 += __shfl_xor_sync(0xffffffffu, d0, off);
                d1 += __shfl_xor_sync(0xffffffffu, d1, off);
                d2 += __shfl_xor_sync(0xffffffffu, d2, off);
            }
            if (lane == 0) {
                g_G[row * 3 + 0] = 1.f / (1.f + expf(-(d0 + b0)));
                g_G[row * 3 + 1] = 1.f / (1.f + expf(-(d1 + b1)));
                g_G[row * 3 + 2] = 1.f / (1.f + expf(-(d2 + b2)));
            }
        }
        return;
    }

    // ---- projection path: 64 rows x 128 cols per block
    extern __shared__ float smem[];
    float*  xs = smem;                       // 64 x 128 floats (32KB)
    float4* wt = (float4*)(smem + 64 * ND);  // 32 x 128 units of 16B (64KB)

    const int tile = blockIdx.x;
    const float* __restrict__ W = (mat == 0) ? Wk : (mat == 1) ? Wv : Wq;
    float* out = (mat == 0) ? g_K : (mat == 1) ? g_V : g_Q;

    const float4* x4 = (const float4*)(x + (size_t)tile * 64 * ND);
#pragma unroll
    for (int j = 0; j < 8; j++) {
        int idx = tid + j * 256;            // 2048 float4s
        ((float4*)xs)[idx] = x4[idx];
    }
#pragma unroll
    for (int j = 0; j < 16; j++) {
        int u = tid + j * 256;              // 4096 units
        int kq = u >> 7, c = u & 127;
        float4 wv;
        wv.x = W[(4 * kq + 0) * ND + c];
        wv.y = W[(4 * kq + 1) * ND + c];
        wv.z = W[(4 * kq + 2) * ND + c];
        wv.w = W[(4 * kq + 3) * ND + c];
        wt[u] = wv;
    }
    __syncthreads();

    const int lane = tid & 31;
    const int rb   = (tid >> 5) * 8;        // 8 rows per thread
    unsigned long long acc[8][4];
#pragma unroll
    for (int r = 0; r < 8; r++)
#pragma unroll
        for (int c = 0; c < 4; c++) acc[r][c] = 0ull;

#pragma unroll 4
    for (int kq = 0; kq < 32; kq++) {
        ulonglong2 xp[8];
#pragma unroll
        for (int r = 0; r < 8; r++)
            xp[r] = *(const ulonglong2*)&xs[(rb + r) * ND + 4 * kq];
#pragma unroll
        for (int cc = 0; cc < 4; cc++) {
            ulonglong2 wp = ((const ulonglong2*)wt)[kq * ND + lane + 32 * cc];
#pragma unroll
            for (int r = 0; r < 8; r++) {
                acc[r][cc] = fma2(xp[r].x, wp.x, acc[r][cc]);
                acc[r][cc] = fma2(xp[r].y, wp.y, acc[r][cc]);
            }
        }
    }
#pragma unroll
    for (int r = 0; r < 8; r++)
#pragma unroll
        for (int cc = 0; cc < 4; cc++)
            out[(size_t)(tile * 64 + rb + r) * ND + lane + 32 * cc] =
                pairsum(acc[r][cc]);
}

// ---------------------------------------------------------------------------
// Launch 2 (PDL): grid (NCH+1, 8), 128 threads.
//   bx < NCH  -> forward-scan phase 1 (per-chunk 2x2 affine map, CLEN=8)
//   bx == NCH -> backward suffix scans -> cM, cS, tstart (per batch)
// ---------------------------------------------------------------------------
__global__ void bwd_p1_kernel() {
#if __CUDA_ARCH__ >= 900
    cudaGridDependencySynchronize();
#endif
    const int bx = blockIdx.x, b = blockIdx.y;

    if (bx < NCH) {
        // ---------------- phase 1: chunk affine maps ----------------
        const int ch = bx, d = threadIdx.x;
        const int t0 = ch * CLEN;
        __shared__ float sg[CLEN * 3];
        if (d < CLEN * 3) sg[d] = g_G[(size_t)b * NS * 3 + t0 * 3 + d];
        __syncthreads();

        const size_t base = (size_t)b * NS * ND + d;
        float kv[CLEN], vv[CLEN];
#pragma unroll
        for (int j = 0; j < CLEN; j++) kv[j] = g_K[base + (size_t)(t0 + j) * ND];
#pragma unroll
        for (int j = 0; j < CLEN; j++) vv[j] = g_V[base + (size_t)(t0 + j) * ND];

        float m00 = 1.f, m01 = 0.f, m10 = 0.f, m11 = 1.f, w0 = 0.f, w1 = 0.f;
#pragma unroll
        for (int j = 0; j < CLEN; j++) {
            float k = kv[j], v = vv[j];
            float a = sg[j * 3 + 0], e = sg[j * 3 + 1], th = sg[j * 3 + 2];
            float thk2 = th * (k * k);
            float p = (1.f - a) - thk2;
            float q = -thk2;
            float c = th * k * v;
            float e10 = e * m10, e11 = e * m11, ev = fmaf(e, w1, c);
            float n00 = fmaf(p, m00, e10), n01 = fmaf(p, m01, e11);
            float n10 = fmaf(q, m00, e10), n11 = fmaf(q, m01, e11);
            float nv0 = fmaf(p, w0, ev),   nv1 = fmaf(q, w0, ev);
            m00 = n00; m01 = n01; m10 = n10; m11 = n11; w0 = nv0; w1 = nv1;
        }
        const size_t cb = ((size_t)(b * NCH + ch) * 6) * ND + d;
        g_comp[cb + 0 * ND] = m00; g_comp[cb + 1 * ND] = m01;
        g_comp[cb + 2 * ND] = m10; g_comp[cb + 3 * ND] = m11;
        g_comp[cb + 4 * ND] = w0;  g_comp[cb + 5 * ND] = w1;
        return;
    }

    // ---------------- backward suffix scans (per batch) ----------------
    const int i = threadIdx.x;          // 0..127, chunk of 8 timesteps
    const int lo = i * 8;
    const float* __restrict__ gb = g_G + (size_t)b * NS * 3;

    float ev[8], av[8], thv[8];
#pragma unroll
    for (int j = 0; j < 8; j++) {
        av[j]  = 1.f - gb[(lo + j) * 3 + 0];
        ev[j]  = gb[(lo + j) * 3 + 1];
        thv[j] = gb[(lo + j) * 3 + 2];
    }
    float e_next = (lo + 8 < NS) ? gb[(lo + 8) * 3 + 1] : 0.f;

    __shared__ float sLe[128], sLa[128], sAa[128], sBa[128];
    __shared__ float sTe[128], sTa[128], sTw[128];
    __shared__ int   smin[4];

    float Le = 1.f, La = 1.f;
#pragma unroll
    for (int j = 0; j < 8; j++) { Le *= ev[j]; La *= av[j]; }
    sLe[i] = Le; sLa[i] = La;
    __syncthreads();
    if (i == 0) {       // exclusive suffix products across chunks
        float te = 1.f, ta = 1.f;
        for (int c = 127; c >= 0; c--) {
            sTe[c] = te; sTa[c] = ta;
            te *= sLe[c]; ta *= sLa[c];
        }
    }
    __syncthreads();

    float E[8], A[8];
    {
        float re = sTe[i], ra = sTa[i];
#pragma unroll
        for (int j = 7; j >= 0; j--) {
            E[j] = re; A[j] = ra;
            re *= ev[j]; ra *= av[j];
        }
    }
    float Aa = 1.f, Ba = 0.f;
#pragma unroll
    for (int j = 7; j >= 0; j--) {
        float al = (j == 7) ? e_next : ev[j + 1];
        Aa = al * Aa;
        Ba = fmaf(al, Ba, A[j]);
    }
    sAa[i] = Aa; sBa[i] = Ba;
    __syncthreads();
    if (i == 0) {       // tail W per chunk
        float w = 0.f;
        for (int c = 127; c >= 0; c--) {
            sTw[c] = w;
            w = fmaf(sAa[c], w, sBa[c]);
        }
    }
    __syncthreads();

    float w = sTw[i];
    int flag = 0;
#pragma unroll
    for (int j = 7; j >= 0; j--) {
        float al = (j == 7) ? e_next : ev[j + 1];
        w = fmaf(al, w, A[j]);                  // = W_{lo+j}
        float cm = -thv[j] * w;
        float cs = -thv[j] * E[j];
        g_cM[b * NS + lo + j] = cm;
        g_cS[b * NS + lo + j] = cs;
        if (fabsf(cm) > 1e-18f || fabsf(cs) > 1e-18f) flag = 1;
    }
    int myv = flag ? lo : 0x7FFFFFFF;
    myv = __reduce_min_sync(0xffffffffu, myv);
    if ((i & 31) == 0) smin[i >> 5] = myv;
    __syncthreads();
    if (i == 0) {
        int r = smin[0];
        r = min(r, smin[1]); r = min(r, smin[2]); r = min(r, smin[3]);
        g_tstart[b] = r;
    }
}

// ---------------------------------------------------------------------------
// Launch 3 (PDL): chunk-boundary start states, hierarchical.
// grid 8 (b), 1024 threads = 8 subs x 128 d. Each sub covers 16 chunks.
// ---------------------------------------------------------------------------
__global__ void scan_p2() {
#if __CUDA_ARCH__ >= 900
    cudaGridDependencySynchronize();
#endif
    const int b   = blockIdx.x;
    const int d   = threadIdx.x & 127;
    const int sub = threadIdx.x >> 7;     // 0..7

    __shared__ float scomp[8][128][6];
    __shared__ float sx[8][128][2];

    // pass A: compose this sub-block's 16 chunk maps
    {
        float r00 = 1.f, r01 = 0.f, r10 = 0.f, r11 = 1.f, rv0 = 0.f, rv1 = 0.f;
#pragma unroll
        for (int i = 0; i < 16; i++) {
            const int c = sub * 16 + i;
            const size_t cb = ((size_t)(b * NCH + c) * 6) * ND + d;
            float t00 = g_comp[cb + 0 * ND], t01 = g_comp[cb + 1 * ND];
            float t10 = g_comp[cb + 2 * ND], t11 = g_comp[cb + 3 * ND];
            float tv0 = g_comp[cb + 4 * ND], tv1 = g_comp[cb + 5 * ND];
            float n00 = fmaf(t00, r00, t01 * r10);
            float n01 = fmaf(t00, r01, t01 * r11);
            float n10 = fmaf(t10, r00, t11 * r10);
            float n11 = fmaf(t10, r01, t11 * r11);
            float nv0 = fmaf(t00, rv0, fmaf(t01, rv1, tv0));
            float nv1 = fmaf(t10, rv0, fmaf(t11, rv1, tv1));
            r00 = n00; r01 = n01; r10 = n10; r11 = n11; rv0 = nv0; rv1 = nv1;
        }
        scomp[sub][d][0] = r00; scomp[sub][d][1] = r01;
        scomp[sub][d][2] = r10; scomp[sub][d][3] = r11;
        scomp[sub][d][4] = rv0; scomp[sub][d][5] = rv1;
    }
    __syncthreads();

    // serial across 8 subs (128 threads, one per d)
    if (threadIdx.x < 128) {
        float x0 = 0.f, x1 = 0.f;
#pragma unroll
        for (int s = 0; s < 8; s++) {
            sx[s][d][0] = x0; sx[s][d][1] = x1;
            float t00 = scomp[s][d][0], t01 = scomp[s][d][1];
            float t10 = scomp[s][d][2], t11 = scomp[s][d][3];
            float nx0 = fmaf(t00, x0, fmaf(t01, x1, scomp[s][d][4]));
            float nx1 = fmaf(t10, x0, fmaf(t11, x1, scomp[s][d][5]));
            x0 = nx0; x1 = nx1;
        }
    }
    __syncthreads();

    // pass B: walk 16 chunks, emit per-chunk start state
    {
        float x0 = sx[sub][d][0], x1 = sx[sub][d][1];
#pragma unroll
        for (int i = 0; i < 16; i++) {
            const int c = sub * 16 + i;
            const size_t sb = ((size_t)(b * NCH + c) * 2) * ND + d;
            g_start[sb] = x0; g_start[sb + ND] = x1;
            const size_t cb = ((size_t)(b * NCH + c) * 6) * ND + d;
            float t00 = g_comp[cb + 0 * ND], t01 = g_comp[cb + 1 * ND];
            float t10 = g_comp[cb + 2 * ND], t11 = g_comp[cb + 3 * ND];
            float nx0 = fmaf(t00, x0, fmaf(t01, x1, g_comp[cb + 4 * ND]));
            float nx1 = fmaf(t10, x0, fmaf(t11, x1, g_comp[cb + 5 * ND]));
            x0 = nx0; x1 = nx1;
        }
    }
}

// ---------------------------------------------------------------------------
// Launch 4 (PDL): replay each chunk from its start state, emit y / err.
// grid (128, 8), 128 threads. Err stores gated by per-batch active range.
// ---------------------------------------------------------------------------
__global__ void scan_p3(float* __restrict__ y_out) {
#if __CUDA_ARCH__ >= 900
    cudaGridDependencySynchronize();
#endif
    const int ch = blockIdx.x, b = blockIdx.y;
    const int d  = threadIdx.x;
    const int t0 = ch * CLEN;
    __shared__ float sg[CLEN * 3];
    __shared__ int sts;
    if (d < CLEN * 3) sg[d] = g_G[(size_t)b * NS * 3 + t0 * 3 + d];
    if (d == 127) sts = g_tstart[b];
    __syncthreads();

    int ts = sts;
    if (ts > NS) ts = NS;
    const bool storeErr = (t0 + CLEN) > (ts & ~31);

    const size_t base = (size_t)b * NS * ND + d;
    const size_t sb = ((size_t)(b * NCH + ch) * 2) * ND + d;
    float m = g_start[sb], s = g_start[sb + ND];

    float kv[CLEN], vv[CLEN], qv[CLEN];
#pragma unroll
    for (int j = 0; j < CLEN; j++) kv[j] = g_K[base + (size_t)(t0 + j) * ND];
#pragma unroll
    for (int j = 0; j < CLEN; j++) vv[j] = g_V[base + (size_t)(t0 + j) * ND];
#pragma unroll
    for (int j = 0; j < CLEN; j++) qv[j] = g_Q[base + (size_t)(t0 + j) * ND];

#pragma unroll
    for (int j = 0; j < CLEN; j++) {
        const size_t off = base + (size_t)(t0 + j) * ND;
        float a = sg[j * 3 + 0], e = sg[j * 3 + 1], th = sg[j * 3 + 2];
        y_out[off] = qv[j] * m;
        float err = fmaf(kv[j], m, -vv[j]);
        if (storeErr) g_Err[off] = err;
        s = fmaf(e, s, -th * (kv[j] * err));
        m = fmaf(1.f - a, m, s);
    }
}

// ---------------------------------------------------------------------------
// Launch 5 (PDL): M_final/S_final = (c o K)^T @ Err over [t_start, NS).
// grid (2 col-halves, 2 which, 8 b), 256 threads, no atomics.
// ---------------------------------------------------------------------------
__global__ void final_kernel(float* __restrict__ out) {
#if __CUDA_ARCH__ >= 900
    cudaGridDependencySynchronize();
#endif
    const int colh  = blockIdx.x;
    const int which = blockIdx.y;     // 0 -> M (cM), 1 -> S (cS)
    const int b     = blockIdx.z;
    const float* __restrict__ cw = which ? g_cS : g_cM;
    const int tid = threadIdx.x;

    int ts = g_tstart[b];
    if (ts > NS) ts = NS;
    int t0 = ts & ~31;

    __shared__ float As[32][128];
    __shared__ float Bs[32][64];

    const int tx = tid & 15, ty = tid >> 4;
    const int i0 = ty * 8, j0 = tx * 4;
    float acc[8][4];
#pragma unroll
    for (int r = 0; r < 8; r++)
#pragma unroll
        for (int c = 0; c < 4; c++) acc[r][c] = 0.f;

    for (int tc = t0; tc < NS; tc += 32) {
        __syncthreads();
        for (int idx = tid; idx < 32 * 128; idx += 256) {
            int kk = idx >> 7, col = idx & 127;
            size_t t = (size_t)b * NS + tc + kk;
            As[kk][col] = cw[t] * g_K[t * ND + col];
        }
        for (int idx = tid; idx < 32 * 64; idx += 256) {
            int kk = idx >> 6, col = idx & 63;
            size_t t = (size_t)b * NS + tc + kk;
            Bs[kk][col] = g_Err[t * ND + colh * 64 + col];
        }
        __syncthreads();

#pragma unroll 8
        for (int kk = 0; kk < 32; kk++) {
            float avv[8], bvv[4];
            float4 a0 = *(const float4*)&As[kk][i0];
            float4 a1 = *(const float4*)&As[kk][i0 + 4];
            float4 b0 = *(const float4*)&Bs[kk][j0];
            avv[0]=a0.x; avv[1]=a0.y; avv[2]=a0.z; avv[3]=a0.w;
            avv[4]=a1.x; avv[5]=a1.y; avv[6]=a1.z; avv[7]=a1.w;
            bvv[0]=b0.x; bvv[1]=b0.y; bvv[2]=b0.z; bvv[3]=b0.w;
#pragma unroll
            for (int r = 0; r < 8; r++)
#pragma unroll
                for (int c = 0; c < 4; c++)
                    acc[r][c] = fmaf(avv[r], bvv[c], acc[r][c]);
        }
    }

    float* o = out + (size_t)NBS * ND + (size_t)which * NB * ND * ND
                 + (size_t)b * ND * ND + colh * 64;
#pragma unroll
    for (int r = 0; r < 8; r++) {
        float4 res = make_float4(acc[r][0], acc[r][1], acc[r][2], acc[r][3]);
        *(float4*)&o[(i0 + r) * ND + j0] = res;
    }
}

// ---------------------------------------------------------------------------
// PDL launch helper: programmatic stream serialization so each dependent
// grid ramps up while its producer drains (graph-capturable).
// ---------------------------------------------------------------------------
template <typename K, typename... Args>
static void launch_pdl(dim3 grid, dim3 block, K kern, Args... args) {
    cudaLaunchConfig_t cfg = {};
    cudaLaunchAttribute attr[1];
    attr[0].id = cudaLaunchAttributeProgrammaticStreamSerialization;
    attr[0].val.programmaticStreamSerializationAllowed = 1;
    cfg.gridDim = grid;
    cfg.blockDim = block;
    cfg.dynamicSmemBytes = 0;
    cfg.stream = 0;
    cfg.attrs = attr;
    cfg.numAttrs = 1;
    cudaLaunchKernelEx(&cfg, kern, args...);
}

extern "C" void kernel_launch(void* const* d_in, const int* in_sizes, int n_in,
                              void* d_out, int out_size) {
    const float* x  = (const float*)d_in[0];
    const float* Wk = (const float*)d_in[1];
    const float* Wv = (const float*)d_in[2];
    const float* Wq = (const float*)d_in[3];
    const float* Wg = (const float*)d_in[4];
    const float* bg = (const float*)d_in[5];
    float* out = (float*)d_out;

    const int proj_smem = (64 * ND + 32 * ND * 4) * (int)sizeof(float); // 96KB
    cudaFuncSetAttribute(proj_gates_kernel,
                         cudaFuncAttributeMaxDynamicSharedMemorySize, proj_smem);

    proj_gates_kernel<<<dim3(128, 4), 256, proj_smem>>>(x, Wk, Wv, Wq, Wg, bg);
    launch_pdl(dim3(NCH + 1, NB), dim3(128), bwd_p1_kernel);
    launch_pdl(dim3(NB), dim3(1024), scan_p2);
    launch_pdl(dim3(NCH, NB), dim3(128), scan_p3, out);
    launch_pdl(dim3(2, 2, 8), dim3(256), final_kernel, out);
}